// round 2
// baseline (speedup 1.0000x reference)
#include <cuda_runtime.h>
#include <cuda_bf16.h>
#include <math_constants.h>

// SupPixPool: out[b][c][k] = max over pixels p with spx[b][p]==k of img[b][c][p]
// B=4, C=64, H=W=512 (HW=262144), K=1024.
//
// Bias values by +128.0f -> all stored floats positive -> float ordering ==
// signed-int-bit ordering -> single atomicMax(int*) per element.
// Per-block SMEM privatization over an 8-channel group (32KB), merge into
// d_out (as int accumulator) with global atomicMax; the LAST block of each
// (b, channel-group) decodes its slice in place (subtract bias).

#define HW   (512 * 512)
#define KSEG 1024
#define CTOT 64
#define BTOT 4
#define CGRP 8            // channels per block
#define NCG  (CTOT / CGRP)
#define PB   16           // pixel-range blocks per (b, channel-group)
#define PIX_PER_BLK (HW / PB)   // 16384
#define BIAS 128.0f
#define NEG_INF_BITS 0xFF800000u

__device__ int g_tickets[BTOT * NCG];   // completion counters, zeroed by init

__global__ void __launch_bounds__(256) sp_init_kernel(uint4* __restrict__ out) {
    const uint4 v = make_uint4(NEG_INF_BITS, NEG_INF_BITS, NEG_INF_BITS, NEG_INF_BITS);
    out[blockIdx.x * 256 + threadIdx.x] = v;   // 256 blocks x 256 thr x 16B = 1MB
    if (blockIdx.x == 0 && threadIdx.x < BTOT * NCG)
        g_tickets[threadIdx.x] = 0;
}

__global__ void __launch_bounds__(256) sp_main_kernel(const float* __restrict__ img,
                                                      const int*   __restrict__ spx,
                                                      int*         __restrict__ out) {
    __shared__ int sm[CGRP * KSEG];   // 32 KB

    #pragma unroll
    for (int i = threadIdx.x; i < CGRP * KSEG; i += 256)
        sm[i] = (int)NEG_INF_BITS;
    __syncthreads();

    const int b  = blockIdx.z;
    const int cg = blockIdx.y;
    const int p0 = blockIdx.x * PIX_PER_BLK;

    const int*   spxb = spx + b * HW + p0;
    const float* imgb = img + ((size_t)(b * CTOT + cg * CGRP)) * HW + p0;

    // 256 threads x 4-wide vectors = 1024 pixels per iteration; 16 iterations.
    #pragma unroll 2
    for (int it = 0; it < PIX_PER_BLK / 1024; ++it) {
        const int base = (it * 256 + threadIdx.x) * 4;
        const int4 s4 = *reinterpret_cast<const int4*>(spxb + base);

        #pragma unroll
        for (int c = 0; c < CGRP; ++c) {
            const float4 v = *reinterpret_cast<const float4*>(imgb + (size_t)c * HW + base);
            atomicMax(&sm[c * KSEG + s4.x], __float_as_int(v.x + BIAS));
            atomicMax(&sm[c * KSEG + s4.y], __float_as_int(v.y + BIAS));
            atomicMax(&sm[c * KSEG + s4.z], __float_as_int(v.z + BIAS));
            atomicMax(&sm[c * KSEG + s4.w], __float_as_int(v.w + BIAS));
        }
    }
    __syncthreads();

    // Merge SMEM partials into global accumulator (d_out viewed as int).
    int* outg = out + (b * CTOT + cg * CGRP) * KSEG;
    #pragma unroll
    for (int i = threadIdx.x; i < CGRP * KSEG; i += 256)
        atomicMax(&outg[i], sm[i]);

    // Last block of this (b, cg) decodes the slice: biased int bits -> float - BIAS.
    __threadfence();
    __shared__ int is_last;
    if (threadIdx.x == 0)
        is_last = (atomicAdd(&g_tickets[b * NCG + cg], 1) == PB - 1);
    __syncthreads();

    if (is_last) {
        float* outf = reinterpret_cast<float*>(outg);
        #pragma unroll
        for (int i = threadIdx.x * 4; i < CGRP * KSEG; i += 256 * 4) {
            // L2 load (bypass L1): values were written by global atomics.
            int4 w = __ldcg(reinterpret_cast<const int4*>(outg + i));
            float4 f;
            f.x = __int_as_float(w.x) - BIAS;
            f.y = __int_as_float(w.y) - BIAS;
            f.z = __int_as_float(w.z) - BIAS;
            f.w = __int_as_float(w.w) - BIAS;
            *reinterpret_cast<float4*>(outf + i) = f;
        }
    }
}

extern "C" void kernel_launch(void* const* d_in, const int* in_sizes, int n_in,
                              void* d_out, int out_size) {
    const float* img = (const float*)d_in[0];   // [4, 64, 512, 512] f32
    const int*   spx = (const int*)d_in[1];     // [4, 512, 512] i32

    // 262144 floats = 65536 uint4; 256 blocks x 256 threads
    sp_init_kernel<<<256, 256>>>((uint4*)d_out);

    dim3 grid(PB, NCG, BTOT);                   // 16 x 8 x 4 = 512 blocks
    sp_main_kernel<<<grid, 256>>>(img, spx, (int*)d_out);
}